// round 6
// baseline (speedup 1.0000x reference)
#include <cuda_runtime.h>

#define DIM      1024
#define NSTAGES  10
#define NTRIG    (NSTAGES * 512)          // 5120 float2 = 40 KB (permuted layout)

// smem: 40KB permuted trig + 16KB exchange (8 warps x 512 floats)
#define SMEM_BYTES (NTRIG * 8 + 8 * 512 * 4)   // 57344

// Permuted trig: entry (s, t6, b) = {cos,sin} for butterfly b of thread t6
// (t6 = w*32+lane within a warp-pair) at stage s, per the phase mappings below.
__device__ float2 g_trig[NTRIG];

__device__ __forceinline__ int insert0(int b, int k)
{
    return ((b >> k) << (k + 1)) | (b & ((1 << k) - 1));
}

// Phase mappings (element index p, 10 bits):
//  P1: p = w*512 + c*128 + lane*4 + j          regs r=(c<<2)|j : bits {8,7,1,0}
//  P2: p = (lane&3) + 4r + 64*(lane>>2) + 512w regs = bits {5,4,3,2}
//  P3: p = lane + 32w + 64r                    regs = bits {9,8,7,6}
__global__ void build_trig_kernel(const float* __restrict__ angles)
{
    int idx = blockIdx.x * 256 + threadIdx.x;
    if (idx >= NTRIG) return;
    int s    = idx >> 9;
    int rem  = idx & 511;
    int t6   = rem >> 3;
    int b    = rem & 7;
    int w    = t6 >> 5;
    int lane = t6 & 31;
    int k    = (s < 2) ? s : (s < 6 ? s - 2 : s - 6);
    int rL   = insert0(b, k);
    int p;
    if (s < 2)      p = w * 512 + (rL >> 2) * 128 + lane * 4 + (rL & 3);
    else if (s < 6) p = (lane & 3) + 4 * rL + 64 * (lane >> 2) + 512 * w;
    else            p = lane + 32 * w + 64 * rL;
    int ti = ((p >> (s + 1)) << s) | (p & ((1 << s) - 1));
    float sv, cv;
    sincosf(angles[s * 512 + ti], &sv, &cv);
    g_trig[idx] = make_float2(cv, sv);
}

__device__ __forceinline__ void rot(float& L, float& R, float c, float s)
{
    float l = L;
    L = fmaf(c, l,  s * R);
    R = fmaf(c, R, -s * l);
}

// One register-local stage: 8 full butterflies per thread on both rows,
// trig = 8 contiguous float2 (4 LDS.128), zero index math.
template<int K>
__device__ __forceinline__ void do_stage(float* vA, float* vB, const float2* tb)
{
    const float4* t4 = (const float4*)tb;
    float4 q0 = t4[0], q1 = t4[1], q2 = t4[2], q3 = t4[3];
    const float cs[8] = {q0.x,q0.z,q1.x,q1.z,q2.x,q2.z,q3.x,q3.z};
    const float sn[8] = {q0.y,q0.w,q1.y,q1.w,q2.y,q2.w,q3.y,q3.w};
    #pragma unroll
    for (int b = 0; b < 8; b++) {
        const int rL = ((b >> K) << (K + 1)) | (b & ((1 << K) - 1));
        const int rR = rL | (1 << K);
        rot(vA[rL], vA[rR], cs[b], sn[b]);
        rot(vB[rL], vB[rR], cs[b], sn[b]);
    }
}

// E1: intra-warp remap P1 -> P2 through the warp's 512-float smem segment.
// XOR swizzle addr = q ^ (((q>>6)&7)<<2): conflict-free writes AND reads.
__device__ __forceinline__ void exch1(float* v, float* seg, int lane)
{
    #pragma unroll
    for (int c = 0; c < 4; c++) {
        int q0 = c * 128 + lane * 4;
        int a  = q0 ^ (((q0 >> 6) & 7) << 2);
        *(float4*)(seg + a) = make_float4(v[4*c], v[4*c+1], v[4*c+2], v[4*c+3]);
    }
    __syncwarp();
    const int A   = (lane & 3) + 64 * (lane >> 2);
    const int swz = ((lane >> 2) & 7) << 2;
    #pragma unroll
    for (int r = 0; r < 16; r++)
        v[r] = seg[(A + 4 * r) ^ swz];
    __syncwarp();
}

__global__ __launch_bounds__(256, 4) void butterfly_kernel(
    const float* __restrict__ x,
    float* __restrict__ out)
{
    extern __shared__ float smem_raw[];
    float2* s_trig = (float2*)smem_raw;            // 5120 float2
    float*  s_xch  = smem_raw + 2 * NTRIG;         // 4096 floats

    const int tid  = threadIdx.x;
    const int lane = tid & 31;
    const int ww   = tid >> 5;
    const int w    = ww & 1;
    const int pr   = ww >> 1;
    const int t6   = w * 32 + lane;

    // Load permuted trig table into shared.
    {
        const float4* gt = (const float4*)g_trig;
        float4*       st = (float4*)s_trig;
        #pragma unroll
        for (int i = 0; i < NTRIG / 2 / 256; i++)
            st[i * 256 + tid] = gt[i * 256 + tid];
    }
    __syncthreads();

    const int rowA = blockIdx.x * 8 + pr;
    const int rowB = rowA + 4;

    float vA[16], vB[16];

    // -------- Phase 1: coalesced loads + stages 0,1 --------
    const float4* xrA = (const float4*)(x + (size_t)rowA * DIM + w * 512);
    const float4* xrB = (const float4*)(x + (size_t)rowB * DIM + w * 512);
    #pragma unroll
    for (int c = 0; c < 4; c++) {
        float4 a = xrA[c * 32 + lane];
        vA[c*4+0] = a.x; vA[c*4+1] = a.y; vA[c*4+2] = a.z; vA[c*4+3] = a.w;
        float4 b = xrB[c * 32 + lane];
        vB[c*4+0] = b.x; vB[c*4+1] = b.y; vB[c*4+2] = b.z; vB[c*4+3] = b.w;
    }

    const float2* tb = s_trig + t6 * 8;
    do_stage<0>(vA, vB, tb + 0 * 512);
    do_stage<1>(vA, vB, tb + 1 * 512);

    // -------- E1: per-warp remap (intra-warp, syncwarp only) --------
    float* seg = s_xch + ww * 512;
    exch1(vA, seg, lane);
    exch1(vB, seg, lane);

    // -------- Phase 2: stages 2..5 register-local --------
    do_stage<0>(vA, vB, tb + 2 * 512);
    do_stage<1>(vA, vB, tb + 3 * 512);
    do_stage<2>(vA, vB, tb + 4 * 512);
    do_stage<3>(vA, vB, tb + 5 * 512);

    // -------- E2: warp-pair remap P2 -> P3 --------
    float* pseg = s_xch + pr * 1024;
    const int B2   = (lane & 3) + 64 * (lane >> 2) + 512 * w;  // own half only
    const int swz2 = ((lane >> 2) & 7) << 2;
    const int rbase = lane + 32 * w;

    #pragma unroll
    for (int r = 0; r < 16; r++)
        pseg[(B2 + 4 * r) ^ swz2] = vA[r];
    __syncthreads();
    #pragma unroll
    for (int r = 0; r < 16; r++)
        vA[r] = pseg[(rbase + 64 * r) ^ ((r & 7) << 2)];
    __syncthreads();
    #pragma unroll
    for (int r = 0; r < 16; r++)
        pseg[(B2 + 4 * r) ^ swz2] = vB[r];
    __syncthreads();
    #pragma unroll
    for (int r = 0; r < 16; r++)
        vB[r] = pseg[(rbase + 64 * r) ^ ((r & 7) << 2)];

    // -------- Phase 3: stages 6..9 register-local --------
    do_stage<0>(vA, vB, tb + 6 * 512);
    do_stage<1>(vA, vB, tb + 7 * 512);
    do_stage<2>(vA, vB, tb + 8 * 512);
    do_stage<3>(vA, vB, tb + 9 * 512);

    // -------- Store (P3: warp covers 128B per r -> fully coalesced) --------
    float* oA = out + (size_t)rowA * DIM + rbase;
    float* oB = out + (size_t)rowB * DIM + rbase;
    #pragma unroll
    for (int r = 0; r < 16; r++) {
        oA[64 * r] = vA[r];
        oB[64 * r] = vB[r];
    }
}

extern "C" void kernel_launch(void* const* d_in, const int* in_sizes, int n_in,
                              void* d_out, int out_size)
{
    const float* x      = (const float*)d_in[0];
    const float* angles = (const float*)d_in[1];
    float*       out    = (float*)d_out;

    const int n_rows = in_sizes[0] / DIM;     // 16384
    const int blocks = n_rows / 8;            // 2048

    build_trig_kernel<<<(NTRIG + 255) / 256, 256>>>(angles);

    cudaFuncSetAttribute(butterfly_kernel,
                         cudaFuncAttributeMaxDynamicSharedMemorySize, SMEM_BYTES);

    butterfly_kernel<<<blocks, 256, SMEM_BYTES>>>(x, out);
}

// round 7
// speedup vs baseline: 1.4545x; 1.4545x over previous
#include <cuda_runtime.h>

#define DIM      1024
#define NSTAGES  10
#define NTRIG    (NSTAGES * 512)          // 5120 float2 = 40 KB (permuted layout)

// smem: 40KB permuted trig + 16KB exchange (8 warps x 512 floats)
#define SMEM_BYTES (NTRIG * 8 + 8 * 512 * 4)   // 57344

// Permuted, CONFLICT-FREE trig layout:
//   butterfly b of thread t6 (w*32+lane in warp-pair) at stage s lives at
//   float2 slot  s*512 + (b>>1)*128 + t6*2 + (b&1)
// so the k-th float4 load of a stage reads lane-stride 16B (coalesced).
__device__ float2 g_trig[NTRIG];

__device__ __forceinline__ int insert0(int b, int k)
{
    return ((b >> k) << (k + 1)) | (b & ((1 << k) - 1));
}

// Phase mappings (element index p, 10 bits):
//  P1: p = w*512 + c*128 + lane*4 + j          regs r=(c<<2)|j : bits {8,7,1,0}
//  P2: p = (lane&3) + 4r + 64*(lane>>2) + 512w regs = bits {5,4,3,2}
//  P3: p = lane + 32w + 64r                    regs = bits {9,8,7,6}
__global__ void build_trig_kernel(const float* __restrict__ angles)
{
    int idx = blockIdx.x * 256 + threadIdx.x;
    if (idx >= NTRIG) return;
    int s    = idx >> 9;
    int rem  = idx & 511;
    int kk   = rem >> 7;          // float4 group (0..3)
    int t6   = (rem >> 1) & 63;
    int e    = rem & 1;
    int b    = kk * 2 + e;        // butterfly index (0..7)
    int w    = t6 >> 5;
    int lane = t6 & 31;
    int k    = (s < 2) ? s : (s < 6 ? s - 2 : s - 6);
    int rL   = insert0(b, k);
    int p;
    if (s < 2)      p = w * 512 + (rL >> 2) * 128 + lane * 4 + (rL & 3);
    else if (s < 6) p = (lane & 3) + 4 * rL + 64 * (lane >> 2) + 512 * w;
    else            p = lane + 32 * w + 64 * rL;
    int ti = ((p >> (s + 1)) << s) | (p & ((1 << s) - 1));
    float sv, cv;
    sincosf(angles[s * 512 + ti], &sv, &cv);
    g_trig[idx] = make_float2(cv, sv);
}

__device__ __forceinline__ void rot(float& L, float& R, float c, float s)
{
    float l = L;
    L = fmaf(c, l,  s * R);
    R = fmaf(c, R, -s * l);
}

// One register-local stage: 8 butterflies/thread on both rows.
// tb4 = (float4*)(s_trig + s*512) + t6 ; group k at tb4[k*64] (lane-stride 16B).
template<int K>
__device__ __forceinline__ void do_stage(float* vA, float* vB, const float4* tb4)
{
    float4 q0 = tb4[0], q1 = tb4[64], q2 = tb4[128], q3 = tb4[192];
    const float cs[8] = {q0.x,q0.z,q1.x,q1.z,q2.x,q2.z,q3.x,q3.z};
    const float sn[8] = {q0.y,q0.w,q1.y,q1.w,q2.y,q2.w,q3.y,q3.w};
    #pragma unroll
    for (int b = 0; b < 8; b++) {
        const int rL = ((b >> K) << (K + 1)) | (b & ((1 << K) - 1));
        const int rR = rL | (1 << K);
        rot(vA[rL], vA[rR], cs[b], sn[b]);
        rot(vB[rL], vB[rR], cs[b], sn[b]);
    }
}

// E1: intra-warp remap P1 -> P2 through the warp's 512-float smem segment.
// XOR swizzle addr = q ^ (((q>>6)&7)<<2): conflict-free writes AND reads.
__device__ __forceinline__ void exch1(float* v, float* seg, int lane)
{
    #pragma unroll
    for (int c = 0; c < 4; c++) {
        int q0 = c * 128 + lane * 4;
        int a  = q0 ^ (((q0 >> 6) & 7) << 2);
        *(float4*)(seg + a) = make_float4(v[4*c], v[4*c+1], v[4*c+2], v[4*c+3]);
    }
    __syncwarp();
    const int A   = (lane & 3) + 64 * (lane >> 2);
    const int swz = ((lane >> 2) & 7) << 2;
    #pragma unroll
    for (int r = 0; r < 16; r++)
        v[r] = seg[(A + 4 * r) ^ swz];
    __syncwarp();
}

__global__ __launch_bounds__(256, 4) void butterfly_kernel(
    const float* __restrict__ x,
    float* __restrict__ out,
    int n_blocks8)                       // n_rows / 8
{
    extern __shared__ float smem_raw[];
    float2* s_trig = (float2*)smem_raw;            // 5120 float2
    float*  s_xch  = smem_raw + 2 * NTRIG;         // 4096 floats

    const int tid  = threadIdx.x;
    const int lane = tid & 31;
    const int ww   = tid >> 5;
    const int w    = ww & 1;
    const int pr   = ww >> 1;
    const int t6   = w * 32 + lane;

    // One-time trig table copy (amortized over the persistent loop).
    {
        const float4* gt = (const float4*)g_trig;
        float4*       st = (float4*)s_trig;
        #pragma unroll
        for (int i = 0; i < NTRIG / 2 / 256; i++)
            st[i * 256 + tid] = gt[i * 256 + tid];
    }
    __syncthreads();

    const float4* tb4 = (const float4*)s_trig + t6;   // + s*256 per stage

    for (int blk = blockIdx.x; blk < n_blocks8; blk += gridDim.x) {
        const int rowA = blk * 8 + pr;
        const int rowB = rowA + 4;

        float vA[16], vB[16];

        // -------- Phase 1: coalesced loads + stages 0,1 --------
        const float4* xrA = (const float4*)(x + (size_t)rowA * DIM + w * 512);
        const float4* xrB = (const float4*)(x + (size_t)rowB * DIM + w * 512);
        #pragma unroll
        for (int c = 0; c < 4; c++) {
            float4 a = xrA[c * 32 + lane];
            vA[c*4+0] = a.x; vA[c*4+1] = a.y; vA[c*4+2] = a.z; vA[c*4+3] = a.w;
            float4 b = xrB[c * 32 + lane];
            vB[c*4+0] = b.x; vB[c*4+1] = b.y; vB[c*4+2] = b.z; vB[c*4+3] = b.w;
        }

        do_stage<0>(vA, vB, tb4 + 0 * 256);
        do_stage<1>(vA, vB, tb4 + 1 * 256);

        // -------- E1: per-warp remap (intra-warp, syncwarp only) --------
        float* seg = s_xch + ww * 512;
        exch1(vA, seg, lane);
        exch1(vB, seg, lane);

        // -------- Phase 2: stages 2..5 register-local --------
        do_stage<0>(vA, vB, tb4 + 2 * 256);
        do_stage<1>(vA, vB, tb4 + 3 * 256);
        do_stage<2>(vA, vB, tb4 + 4 * 256);
        do_stage<3>(vA, vB, tb4 + 5 * 256);

        // -------- E2: warp-pair remap P2 -> P3 --------
        float* pseg = s_xch + pr * 1024;
        const int B2    = (lane & 3) + 64 * (lane >> 2) + 512 * w;
        const int swz2  = ((lane >> 2) & 7) << 2;
        const int rbase = lane + 32 * w;

        #pragma unroll
        for (int r = 0; r < 16; r++)
            pseg[(B2 + 4 * r) ^ swz2] = vA[r];
        __syncthreads();
        #pragma unroll
        for (int r = 0; r < 16; r++)
            vA[r] = pseg[(rbase + 64 * r) ^ ((r & 7) << 2)];
        __syncthreads();
        #pragma unroll
        for (int r = 0; r < 16; r++)
            pseg[(B2 + 4 * r) ^ swz2] = vB[r];
        __syncthreads();
        #pragma unroll
        for (int r = 0; r < 16; r++)
            vB[r] = pseg[(rbase + 64 * r) ^ ((r & 7) << 2)];

        // -------- Phase 3: stages 6..9 register-local --------
        do_stage<0>(vA, vB, tb4 + 6 * 256);
        do_stage<1>(vA, vB, tb4 + 7 * 256);
        do_stage<2>(vA, vB, tb4 + 8 * 256);
        do_stage<3>(vA, vB, tb4 + 9 * 256);

        // -------- Store (P3: warp covers 128B per r -> fully coalesced) ----
        float* oA = out + (size_t)rowA * DIM + rbase;
        float* oB = out + (size_t)rowB * DIM + rbase;
        #pragma unroll
        for (int r = 0; r < 16; r++) {
            oA[64 * r] = vA[r];
            oB[64 * r] = vB[r];
        }

        // Protect exchange buffer against next iteration's E1 writes.
        __syncthreads();
    }
}

extern "C" void kernel_launch(void* const* d_in, const int* in_sizes, int n_in,
                              void* d_out, int out_size)
{
    const float* x      = (const float*)d_in[0];
    const float* angles = (const float*)d_in[1];
    float*       out    = (float*)d_out;

    const int n_rows    = in_sizes[0] / DIM;   // 16384
    const int n_blocks8 = n_rows / 8;          // 2048

    build_trig_kernel<<<(NTRIG + 255) / 256, 256>>>(angles);

    cudaFuncSetAttribute(butterfly_kernel,
                         cudaFuncAttributeMaxDynamicSharedMemorySize, SMEM_BYTES);

    butterfly_kernel<<<592, 256, SMEM_BYTES>>>(x, out, n_blocks8);
}